// round 13
// baseline (speedup 1.0000x reference)
#include <cuda_runtime.h>
#include <cuda_fp16.h>
#include <cstdint>
#include <math.h>

#define TOK   8192
#define DIM   2048
#define NEXP  8
#define EDIM  1024
#define KFLAT 8192

// ---------------- static device scratch ----------------
__device__ __half g_Xh  [(size_t)TOK * DIM];          // fp16(x)
__device__ __half g_WuTh[(size_t)NEXP * EDIM * DIM];  // [e][f][d] fp16
__device__ __half g_WdTh[(size_t)DIM * KFLAT];        // [n][e*1024+f] fp16
__device__ __half g_Hsh [(size_t)TOK * KFLAT];        // fp16(p*gelu(..))
__device__ float  g_Pr  [(size_t)TOK * NEXP];

// ---------------- helpers ----------------
__device__ __forceinline__ uint32_t smem_u32(const void* p) {
    uint32_t a;
    asm("{ .reg .u64 t; cvta.to.shared.u64 t, %1; cvt.u32.u64 %0, t; }" : "=r"(a) : "l"(p));
    return a;
}
__device__ __forceinline__ float gelu_t(float h) {
    float u  = 0.7978845608028654f * (h + 0.044715f * h * h * h);
    float ex = __expf(2.0f * u);
    float th = 1.0f - __fdividef(2.0f, ex + 1.0f);
    return 0.5f * h * (1.0f + th);
}
__device__ __forceinline__ void cpasync16(uint32_t dst, const void* src) {
    asm volatile("cp.async.cg.shared.global [%0], [%1], 16;" :: "r"(dst), "l"(src));
}
__device__ __forceinline__ void ldsm4(uint32_t* r, uint32_t a) {
    asm volatile("ldmatrix.sync.aligned.m8n8.x4.shared.b16 {%0,%1,%2,%3}, [%4];"
                 : "=r"(r[0]), "=r"(r[1]), "=r"(r[2]), "=r"(r[3]) : "r"(a));
}
// m16n8k16, fp16 inputs, fp16 accumulators. First-of-chunk form: C = zero regs.
__device__ __forceinline__ void mma16h_z(uint32_t* d, const uint32_t* a, uint32_t b0, uint32_t b1,
                                         uint32_t z) {
    asm volatile(
        "mma.sync.aligned.m16n8k16.row.col.f16.f16.f16.f16 "
        "{%0,%1}, {%2,%3,%4,%5}, {%6,%7}, {%8,%8};"
        : "=r"(d[0]), "=r"(d[1])
        : "r"(a[0]), "r"(a[1]), "r"(a[2]), "r"(a[3]), "r"(b0), "r"(b1), "r"(z));
}
__device__ __forceinline__ void mma16h(uint32_t* d, const uint32_t* a, uint32_t b0, uint32_t b1) {
    asm volatile(
        "mma.sync.aligned.m16n8k16.row.col.f16.f16.f16.f16 "
        "{%0,%1}, {%2,%3,%4,%5}, {%6,%7}, {%0,%1};"
        : "+r"(d[0]), "+r"(d[1])
        : "r"(a[0]), "r"(a[1]), "r"(a[2]), "r"(a[3]), "r"(b0), "r"(b1));
}

// ---------------- prep kernels ----------------
// out[z*outE + c*outRow + r] = fp16(in[z*inE + r*C + c])
__global__ void transpose_h_kernel(const float* __restrict__ in, __half* __restrict__ out,
                                   int R, int C, size_t inE, size_t outE, int outRow) {
    __shared__ float tile[32][33];
    const float* ip = in + (size_t)blockIdx.z * inE;
    __half* op = out + (size_t)blockIdx.z * outE;
    int c0 = blockIdx.x * 32, r0 = blockIdx.y * 32;
#pragma unroll
    for (int i = threadIdx.y; i < 32; i += 8)
        tile[i][threadIdx.x] = ip[(size_t)(r0 + i) * C + c0 + threadIdx.x];
    __syncthreads();
#pragma unroll
    for (int i = threadIdx.y; i < 32; i += 8)
        op[(size_t)(c0 + i) * outRow + r0 + threadIdx.x] = __float2half_rn(tile[threadIdx.x][i]);
}

// router (Wr cached in smem pad-9) + fused fp16 conversion of this block's x rows
#define RTR_SMEM (2048 * 9 * 4)
__global__ void router_kernel(const float* __restrict__ x, const float* __restrict__ Wr,
                              const float* __restrict__ br, float* __restrict__ probs,
                              __half2* __restrict__ xh2) {
    extern __shared__ float ws[];
    int tid = threadIdx.x;
    for (int i = tid; i < DIM * 8; i += 256) {
        int k = i >> 3, e = i & 7;
        ws[k * 9 + e] = Wr[i];
    }
    __syncthreads();
    int t = blockIdx.x * 8 + (tid >> 5);
    int lid = tid & 31;
    const float* xr = x + (size_t)t * DIM;
    float acc[8];
#pragma unroll
    for (int e = 0; e < 8; e++) acc[e] = 0.f;
    for (int k = lid; k < DIM; k += 32) {
        float xv = xr[k];
        const float* w = ws + k * 9;
#pragma unroll
        for (int e = 0; e < 8; e++) acc[e] += xv * w[e];
    }
#pragma unroll
    for (int e = 0; e < 8; e++)
#pragma unroll
        for (int o = 16; o > 0; o >>= 1) acc[e] += __shfl_xor_sync(0xffffffffu, acc[e], o);
    if (lid == 0) {
        float m = -1e30f;
#pragma unroll
        for (int e = 0; e < 8; e++) { acc[e] += br[e]; m = fmaxf(m, acc[e]); }
        float s = 0.f;
#pragma unroll
        for (int e = 0; e < 8; e++) { acc[e] = expf(acc[e] - m); s += acc[e]; }
        float inv = 1.f / s;
#pragma unroll
        for (int e = 0; e < 8; e++) probs[(size_t)t * 8 + e] = acc[e] * inv;
    }
    // fused x -> fp16 for this block's 8 tokens (x rows are L2-hot)
    size_t base2 = (size_t)blockIdx.x * 8 * (DIM / 2);
    const float2* x2 = (const float2*)(x + (size_t)blockIdx.x * 8 * DIM);
#pragma unroll 4
    for (int i = tid; i < 8 * DIM / 2; i += 256) {
        float2 v = x2[i];
        xh2[base2 + i] = __floats2half2_rn(v.x, v.y);
    }
}

// ---------------- fp16 mma.sync GEMM, f16 chunk-accumulate + f32 shadow ----------------
// CTA tile 256(M) x 128(N), 256 threads = 8 warps, warp grid 4(M) x 2(N),
// warp tile 64x64. K staged 64 halves/iter (144B row stride), 4 kk-steps/iter.
// f16 accumulators within one kt-iter (K=64), promoted to f32 shadow each iter.
// 4-stage cp.async pipeline, wait_group 2.
#define STG_B     55296
#define SMEM_SZ   221184     // 4 * 55296

// MODE 0: Hsh = fp16(p[t,e0] * gelu(A@B^T + bu))  out half
// MODE 1: out = A@B^T + sum_e p_e*bd_e + x        out float
template<int MODE>
__global__ void __launch_bounds__(256, 1) moe_gemm(
    const __half* __restrict__ A, const __half* __restrict__ Bm, int K,
    const float* __restrict__ probs, const float* __restrict__ bias,
    const float* __restrict__ xres, void* __restrict__ outp)
{
    extern __shared__ float smem[];
    uint32_t sb = smem_u32(smem);
    const int tid = threadIdx.x, wid = tid >> 5, lid = tid & 31;
    const int wm = wid & 3, wn = wid >> 2;          // warp grid 4(M) x 2(N)
    const int m0 = blockIdx.y * 256, n0 = blockIdx.x * 128;
    const int g = lid >> 2, i4 = lid & 3;

    // A fragment base: rows wm*64.., 4 mt groups of 16 rows
    const uint32_t aoff = (uint32_t)((wm * 64 + (lid & 15)) * 144 + ((lid >> 4) * 16));
    // B fragment base: rows (=N cols) wn*64.., 4 P groups of 16
    const uint32_t boff = (uint32_t)(36864 +
        (wn * 64 + ((lid >> 4) & 1) * 8 + (lid & 7)) * 144 + (((lid >> 3) & 1) * 16));

    float d[4][8][4];           // f32 shadow accumulators
#pragma unroll
    for (int a = 0; a < 4; a++)
#pragma unroll
        for (int b = 0; b < 8; b++)
#pragma unroll
            for (int c = 0; c < 4; c++) d[a][b][c] = 0.f;
    uint32_t dh[4][8][2];       // f16 chunk accumulators

    const __half* Ab = A + (size_t)m0 * K;
    const __half* Bb = Bm + (size_t)n0 * K;

    auto load_stage = [&](int st, int kt) {
        uint32_t base = sb + st * STG_B;
        const __half* Ag = Ab + kt * 64;
        const __half* Bg = Bb + kt * 64;
#pragma unroll
        for (int q = 0; q < 12; q++) {
            int ci = q * 256 + tid;
            if (ci < 2048) {
                int r = ci >> 3, c = ci & 7;
                cpasync16(base + r * 144 + c * 16, Ag + (size_t)r * K + c * 8);
            } else {
                int c2 = ci - 2048;
                int r = c2 >> 3, c = c2 & 7;
                cpasync16(base + 36864 + r * 144 + c * 16, Bg + (size_t)r * K + c * 8);
            }
        }
    };

    const int iters = K >> 6;
    load_stage(0, 0);
    asm volatile("cp.async.commit_group;" ::: "memory");
    load_stage(1, 1);
    asm volatile("cp.async.commit_group;" ::: "memory");
    load_stage(2, 2);
    asm volatile("cp.async.commit_group;" ::: "memory");

    for (int kt = 0; kt < iters; kt++) {
        asm volatile("cp.async.wait_group 2;" ::: "memory");
        __syncthreads();
        if (kt + 3 < iters) {
            load_stage((kt + 3) & 3, kt + 3);
        }
        asm volatile("cp.async.commit_group;" ::: "memory");

        uint32_t base = sb + (kt & 3) * STG_B;
#pragma unroll
        for (int kk = 0; kk < 4; kk++) {           // one k16 slice per kk
            uint32_t af[4][4], bf[4][4];
#pragma unroll
            for (int mt = 0; mt < 4; mt++)
                ldsm4(af[mt], base + aoff + mt * (16 * 144) + kk * 32);
#pragma unroll
            for (int P = 0; P < 4; P++)
                ldsm4(bf[P], base + boff + P * (16 * 144) + kk * 32);
            if (kk == 0) {
#pragma unroll
                for (int mt = 0; mt < 4; mt++)
#pragma unroll
                    for (int P = 0; P < 4; P++) {
                        mma16h_z(dh[mt][2 * P],     af[mt], bf[P][0], bf[P][1], 0u);
                        mma16h_z(dh[mt][2 * P + 1], af[mt], bf[P][2], bf[P][3], 0u);
                    }
            } else {
#pragma unroll
                for (int mt = 0; mt < 4; mt++)
#pragma unroll
                    for (int P = 0; P < 4; P++) {
                        mma16h(dh[mt][2 * P],     af[mt], bf[P][0], bf[P][1]);
                        mma16h(dh[mt][2 * P + 1], af[mt], bf[P][2], bf[P][3]);
                    }
            }
        }
        // promote f16 chunk sums into f32 shadow
#pragma unroll
        for (int mt = 0; mt < 4; mt++)
#pragma unroll
            for (int nt = 0; nt < 8; nt++) {
                float2 lo = __half22float2(*reinterpret_cast<__half2*>(&dh[mt][nt][0]));
                float2 hi = __half22float2(*reinterpret_cast<__half2*>(&dh[mt][nt][1]));
                d[mt][nt][0] += lo.x; d[mt][nt][1] += lo.y;
                d[mt][nt][2] += hi.x; d[mt][nt][3] += hi.y;
            }
    }

    // ---- epilogue ----
    if (MODE == 0) {
        __half* outh = (__half*)outp;
        int e0 = n0 >> 10;
#pragma unroll
        for (int mt = 0; mt < 4; mt++)
#pragma unroll
            for (int h = 0; h < 2; h++) {
                int rl = wm * 64 + mt * 16 + h * 8 + g;
                float p = probs[(size_t)(m0 + rl) * 8 + e0];
                __half* dst = outh + (size_t)(m0 + rl) * KFLAT + n0;
                const float* bu = bias + (size_t)e0 * EDIM + (n0 & 1023);
#pragma unroll
                for (int nt = 0; nt < 8; nt++) {
                    int nl = wn * 64 + nt * 8 + i4 * 2;
                    float v0 = p * gelu_t(d[mt][nt][h * 2 + 0] + bu[nl]);
                    float v1 = p * gelu_t(d[mt][nt][h * 2 + 1] + bu[nl + 1]);
                    *(__half2*)(dst + nl) = __floats2half2_rn(v0, v1);
                }
            }
    } else {
        float* outf = (float*)outp;
#pragma unroll
        for (int mt = 0; mt < 4; mt++)
#pragma unroll
            for (int h = 0; h < 2; h++) {
                int rl = wm * 64 + mt * 16 + h * 8 + g;
                const float4* pp = (const float4*)(probs + (size_t)(m0 + rl) * 8);
                float4 p0 = pp[0], p1 = pp[1];
                const float* xr = xres + (size_t)(m0 + rl) * DIM + n0;
                float* dst = outf + (size_t)(m0 + rl) * DIM + n0;
#pragma unroll
                for (int nt = 0; nt < 8; nt++) {
                    int nl = wn * 64 + nt * 8 + i4 * 2;
                    float s0 = d[mt][nt][h * 2 + 0];
                    float s1 = d[mt][nt][h * 2 + 1];
#pragma unroll
                    for (int e = 0; e < 8; e++) {
                        float pe = (e == 0) ? p0.x : (e == 1) ? p0.y : (e == 2) ? p0.z :
                                   (e == 3) ? p0.w : (e == 4) ? p1.x : (e == 5) ? p1.y :
                                   (e == 6) ? p1.z : p1.w;
                        const float* bd = bias + (size_t)e * DIM + n0 + nl;
                        s0 += pe * bd[0];
                        s1 += pe * bd[1];
                    }
                    float2 xv = *(const float2*)(xr + nl);
                    float2 v; v.x = s0 + xv.x; v.y = s1 + xv.y;
                    *(float2*)(dst + nl) = v;
                }
            }
    }
}

// ---------------- launch ----------------
extern "C" void kernel_launch(void* const* d_in, const int* in_sizes, int n_in,
                              void* d_out, int out_size) {
    const float* x  = (const float*)d_in[0];
    const float* Wr = (const float*)d_in[1];
    const float* br = (const float*)d_in[2];
    const float* Wu = (const float*)d_in[3];
    const float* bu = (const float*)d_in[4];
    const float* Wd = (const float*)d_in[5];
    const float* bd = (const float*)d_in[6];
    float* out = (float*)d_out;

    __half *Xh, *WuTh, *WdTh, *Hsh;
    float *Pr;
    cudaGetSymbolAddress((void**)&Xh,   g_Xh);
    cudaGetSymbolAddress((void**)&WuTh, g_WuTh);
    cudaGetSymbolAddress((void**)&WdTh, g_WdTh);
    cudaGetSymbolAddress((void**)&Hsh,  g_Hsh);
    cudaGetSymbolAddress((void**)&Pr,   g_Pr);

    cudaFuncSetAttribute(moe_gemm<0>, cudaFuncAttributeMaxDynamicSharedMemorySize, SMEM_SZ);
    cudaFuncSetAttribute(moe_gemm<1>, cudaFuncAttributeMaxDynamicSharedMemorySize, SMEM_SZ);
    cudaFuncSetAttribute(router_kernel, cudaFuncAttributeMaxDynamicSharedMemorySize, RTR_SMEM);

    // 1. WuTh[e][f][d] = fp16(Wu[e][d][f])
    transpose_h_kernel<<<dim3(EDIM / 32, DIM / 32, NEXP), dim3(32, 8)>>>(
        Wu, WuTh, DIM, EDIM, (size_t)DIM * EDIM, (size_t)EDIM * DIM, DIM);
    // 2. WdTh[n][e*1024+f] = fp16(Wd[e][f][n])
    transpose_h_kernel<<<dim3(DIM / 32, EDIM / 32, NEXP), dim3(32, 8)>>>(
        Wd, WdTh, EDIM, DIM, (size_t)EDIM * DIM, (size_t)EDIM, KFLAT);
    // 3. router probs + fused x->fp16
    router_kernel<<<TOK / 8, 256, RTR_SMEM>>>(x, Wr, br, Pr, (__half2*)Xh);
    // 4. up-GEMM + gelu + p -> Hsh (fp16)
    moe_gemm<0><<<dim3(KFLAT / 128, TOK / 256), 256, SMEM_SZ>>>(
        Xh, WuTh, DIM, Pr, bu, nullptr, Hsh);
    // 5. down-GEMM + bias + residual -> out (fp32)
    moe_gemm<1><<<dim3(DIM / 128, TOK / 256), 256, SMEM_SZ>>>(
        Hsh, WdTh, KFLAT, Pr, bd, x, out);
}